// round 1
// baseline (speedup 1.0000x reference)
#include <cuda_runtime.h>
#include <math.h>

#define TPB 128           // threads per block == cells per block
#define CH 30             // channels per cell
#define MAX_BLOCKS 8192

__device__ float g_partials[MAX_BLOCKS];

// Per-cell YOLO loss, exactly matching the jax reference math.
__device__ __forceinline__ float cell_loss(const float* __restrict__ p,
                                           const float* __restrict__ t,
                                           float gy, float gx)
{
    const float ratio = 1.0f / 7.0f;
    const float tconf = t[4];
    const float p1c = p[4], p2c = p[9];

    if (!(tconf > 0.0f)) {
        // no-object cell: only lambda_noobj * (conf1^2 + conf2^2)
        return 0.5f * (p1c * p1c + p2c * p2c);
    }

    // target abs box
    float tcx = (t[0] + gx) * ratio;
    float tcy = (t[1] + gy) * ratio;
    float tw = t[2], th = t[3];
    float tx1 = tcx - tw * 0.5f, ty1 = tcy - th * 0.5f;
    float tx2 = tcx + tw * 0.5f, ty2 = tcy + th * 0.5f;
    float areaT = (tx2 - tx1) * (ty2 - ty1);

    // IoU of predictor box (channels off..off+4) with target
    auto iou_with = [&](const float* b) -> float {
        float bcx = (b[0] + gx) * ratio;
        float bcy = (b[1] + gy) * ratio;
        float bw = b[2], bh = b[3];
        float x1 = bcx - bw * 0.5f, y1 = bcy - bh * 0.5f;
        float x2 = bcx + bw * 0.5f, y2 = bcy + bh * 0.5f;
        float iw = fmaxf(fminf(x2, tx2) - fmaxf(x1, tx1), 0.0f);
        float ih = fmaxf(fminf(y2, ty2) - fmaxf(y1, ty1), 0.0f);
        float inter = iw * ih;
        float area = (x2 - x1) * (y2 - y1);
        return inter / (area + areaT - inter);
    };

    float iou1 = iou_with(p);
    float iou2 = iou_with(p + 5);
    bool resp = iou1 > iou2;
    const float* pc = resp ? p : (p + 5);
    float iouS = resp ? iou1 : iou2;

    // coord xy
    float dx = pc[0] - t[0];
    float dy = pc[1] - t[1];
    // coord wh (sqrt of clipped values)
    float sw = sqrtf(fmaxf(pc[2], 1e-6f)) - sqrtf(fmaxf(t[2], 1e-6f));
    float sh = sqrtf(fmaxf(pc[3], 1e-6f)) - sqrtf(fmaxf(t[3], 1e-6f));
    float coord = 5.0f * (dx * dx + dy * dy + sw * sw + sh * sh);

    // conf (responsible predictor vs its IoU)
    float dc = pc[4] - iouS;
    float conf = dc * dc;

    // class loss over 20 channels
    float cls = 0.0f;
#pragma unroll
    for (int k = 10; k < 30; k++) {
        float d = p[k] - t[k];
        cls += d * d;
    }
    return coord + conf + cls;
}

__global__ void __launch_bounds__(TPB)
yolo_loss_main(const float* __restrict__ predicts,
               const float* __restrict__ targets,
               int n_cells)
{
    __shared__ float sp[TPB * CH];   // 15360 B
    __shared__ float st[TPB * CH];   // 15360 B

    const int tid = threadIdx.x;
    const int tile_cell0 = blockIdx.x * TPB;
    const int cells_here = min(TPB, n_cells - tile_cell0);
    const long long float_base = (long long)tile_cell0 * CH;
    const int n_floats = cells_here * CH;

    // Cooperative coalesced load of the tile into shared memory.
    if (cells_here == TPB) {
        // full tile: 3840 floats = 960 float4 per array; base is 16B-aligned
        const float4* p4 = reinterpret_cast<const float4*>(predicts + float_base);
        const float4* t4 = reinterpret_cast<const float4*>(targets + float_base);
        float4* sp4 = reinterpret_cast<float4*>(sp);
        float4* st4 = reinterpret_cast<float4*>(st);
#pragma unroll
        for (int i = 0; i < (TPB * CH) / 4 / TPB; i++) {   // 7 full rounds
            int idx = i * TPB + tid;
            sp4[idx] = p4[idx];
            st4[idx] = t4[idx];
        }
        // remainder: 960 - 7*128 = 64 float4
        if (tid < 64) {
            int idx = 7 * TPB + tid;
            sp4[idx] = p4[idx];
            st4[idx] = t4[idx];
        }
    } else {
        for (int i = tid; i < n_floats; i += TPB) {
            sp[i] = predicts[float_base + i];
            st[i] = targets[float_base + i];
        }
    }
    __syncthreads();

    float loss = 0.0f;
    if (tid < cells_here) {
        int cell = tile_cell0 + tid;
        int within = cell % 49;        // (y, x) within the 7x7 grid
        int y = within / 7;
        int x = within - y * 7;
        loss = cell_loss(sp + tid * CH, st + tid * CH, (float)y, (float)x);
    }
    __syncthreads();

    // Deterministic block tree reduction (reuse sp as scratch).
    sp[tid] = loss;
    __syncthreads();
#pragma unroll
    for (int s = TPB / 2; s >= 32; s >>= 1) {
        if (tid < s) sp[tid] += sp[tid + s];
        __syncthreads();
    }
    if (tid < 32) {
        float v = sp[tid];
#pragma unroll
        for (int off = 16; off > 0; off >>= 1)
            v += __shfl_down_sync(0xFFFFFFFFu, v, off);
        if (tid == 0) g_partials[blockIdx.x] = v;
    }
}

__global__ void __launch_bounds__(1024)
yolo_loss_final(int n_partials, float* __restrict__ out)
{
    __shared__ float red[1024];
    const int tid = threadIdx.x;
    float v = 0.0f;
    // fixed-order strided accumulation -> deterministic
    for (int i = tid; i < n_partials; i += 1024)
        v += g_partials[i];
    red[tid] = v;
    __syncthreads();
#pragma unroll
    for (int s = 512; s >= 32; s >>= 1) {
        if (tid < s) red[tid] += red[tid + s];
        __syncthreads();
    }
    if (tid < 32) {
        float w = red[tid];
#pragma unroll
        for (int off = 16; off > 0; off >>= 1)
            w += __shfl_down_sync(0xFFFFFFFFu, w, off);
        if (tid == 0) out[0] = w;
    }
}

extern "C" void kernel_launch(void* const* d_in, const int* in_sizes, int n_in,
                              void* d_out, int out_size)
{
    const float* predicts = (const float*)d_in[0];
    const float* targets  = (const float*)d_in[1];
    float* out = (float*)d_out;

    int n_cells = in_sizes[0] / CH;            // 8192*7*7 = 401408
    int blocks = (n_cells + TPB - 1) / TPB;    // 3136
    if (blocks > MAX_BLOCKS) blocks = MAX_BLOCKS;  // safety (not hit for this shape)

    yolo_loss_main<<<blocks, TPB>>>(predicts, targets, n_cells);
    yolo_loss_final<<<1, 1024>>>(blocks, out);
}